// round 16
// baseline (speedup 1.0000x reference)
#include <cuda_runtime.h>

#define NN 207
#define EE 1722
#define TT 24
#define BB 64
#define LL 2048
#define RESV 12
#define L4 (LL / 4)      // 512 float4 per row
#define LT4 32           // float4 per L-tile (= 128 floats)
#define NTHREADS 512     // main kernel: 2 CTAs/SM (~100 KB smem each)
#define NWARPS (NTHREADS / 32)
#define NCH ((EE + 31) / 32)   // 54 edge chunks of 32
#define EEPAD 1930             // to-CSR entries incl. even-padding (EE + NN rounded even)

// ---------------- device scratch (no allocation allowed) ----------------
// EF: {wrn, wrn, wra, noff} — duplicated -wr so LDS.128 lands the FFMA2 pair
// directly in an aligned register pair.
struct __align__(16) EF { float wrn0; float wrn1; float wra; int noff; };
struct __align__(8)  ET { float wdc; int noff; };

__device__ EF     g_ef[TT * EE];         // from-CSR ordered, per t (reaction gathers)
__device__ ET     g_et[TT * EEPAD];      // to-CSR ordered, per t (diffusion gathers, even-padded)
__device__ float4 g_c1[TT * NN];         // (dr, dra, dd+dda+1, br)
__device__ float2 g_c2[TT * NN];         // (bra, bd+bda)
__device__ int    g_from_off[NN + 1];
__device__ int    g_to_off[NN + 1];      // PADDED offsets (bucket sizes rounded to even)

// ---------------- packed helpers ----------------
__device__ __forceinline__ unsigned long long pk2(float a, float b) {
    unsigned long long r;
    asm("mov.b64 %0, {%1, %2};" : "=l"(r) : "f"(a), "f"(b));
    return r;
}
__device__ __forceinline__ unsigned long long pkpair(unsigned a, unsigned b) {
    unsigned long long r;
    asm("mov.b64 %0, {%1, %2};" : "=l"(r) : "r"(a), "r"(b));
    return r;
}
__device__ __forceinline__ void upk2(unsigned long long v, float& a, float& b) {
    asm("mov.b64 {%0, %1}, %2;" : "=f"(a), "=f"(b) : "l"(v));
}
__device__ __forceinline__ void fma2(unsigned long long& d,
                                     unsigned long long a, unsigned long long b) {
    asm("fma.rn.f32x2 %0, %1, %2, %0;" : "+l"(d) : "l"(a), "l"(b));
}
// packed bf16 pair (hi=c1|lo=c0) -> f32x2 {lo=c0, hi=c1}  (bf16 = fp32 high bits)
// The AND is load-bearing: without it the partner bf16's bits land in mantissa
// bits 0-15 (up to 2^-7 relative — same order as bf16 rounding itself).
__device__ __forceinline__ unsigned long long bf2f2(unsigned v) {
    unsigned long long r;
    asm("{\n\t.reg .b32 lo, hi;\n\t"
        "shl.b32 lo, %1, 16;\n\t"
        "and.b32 hi, %1, 0xFFFF0000;\n\t"
        "mov.b64 %0, {lo, hi};\n\t}" : "=l"(r) : "r"(v));
    return r;
}
// pack (c0, c1) fp32 -> bf16x2 (hi=c1, lo=c0), round-to-nearest
__device__ __forceinline__ unsigned f2bf2(float c1, float c0) {
    unsigned r;
    asm("cvt.rn.bf16x2.f32 %0, %1, %2;" : "=r"(r) : "f"(c1), "f"(c0));
    return r;
}
__device__ __forceinline__ float ftanh(float x) {
    float y;
    asm("tanh.approx.f32 %0, %1;" : "=f"(y) : "f"(x));
    return y;
}

// =====================================================================
// FUSED prepass: one block per time slot t. Each block rebuilds the
// deterministic CSR in its own smem (chunk-parallel: counts -> per-node
// chunk prefix -> scan -> match_any) and writes records/coefficients for
// its t directly. Slot order identical to previous rounds (edge-id order).
// NOTE: eid is sized EEPAD — the T side writes at PADDED slots (R15 bug).
// =====================================================================
__global__ __launch_bounds__(512)
void rd_prep(const int* __restrict__ ef, const int* __restrict__ et,
             const float* __restrict__ wr,  const float* __restrict__ wd,
             const float* __restrict__ wra, const float* __restrict__ wda,
             const float* __restrict__ br,  const float* __restrict__ bd,
             const float* __restrict__ bra, const float* __restrict__ bda) {
    extern __shared__ int sh[];
    int* sf  = sh;               // [EE]
    int* st  = sf + EE;          // [EE]
    int* cb  = st + EE;          // [NCH*NN] counts -> chunk bases
    int* eid = cb + NCH * NN;    // [EEPAD] slot -> edge id (reused F then T)
    int* off = eid + EEPAD;      // [NN+1]
    int* tot = off + NN + 1;     // [NN]

    const int t   = blockIdx.x;
    const int tid = threadIdx.x;
    const int lane = tid & 31;
    const int wid  = tid >> 5;
    const int tE  = t * EE;
    const int tN  = t * NN;

    for (int i = tid; i < EE; i += 512) { sf[i] = ef[i]; st[i] = et[i]; }
    for (int i = tid; i < NCH * NN; i += 512) cb[i] = 0;
    __syncthreads();

    float dd1 = 1.f;   // persists across phases (thread tid < NN)

    // ================= F side (from-CSR: reaction records) =================
    for (int i = tid; i < EE; i += 512) atomicAdd(&cb[(i >> 5) * NN + sf[i]], 1);
    __syncthreads();

    if (tid < NN) {
        int run = 0;
        #pragma unroll 6
        for (int c = 0; c < NCH; c++) {
            int v = cb[c * NN + tid]; cb[c * NN + tid] = run; run += v;
        }
        tot[tid] = run;
    }
    __syncthreads();

    if (wid == 0) {
        int carry = 0;
        #pragma unroll
        for (int j = 0; j < (NN + 31) / 32; j++) {
            int idx = j * 32 + lane;
            int v = (idx < NN) ? tot[idx] : 0;
            int s = v;
            #pragma unroll
            for (int d = 1; d < 32; d <<= 1) {
                int u = __shfl_up_sync(0xffffffffu, s, d);
                if (lane >= d) s += u;
            }
            int tsum = __shfl_sync(0xffffffffu, s, 31);
            if (idx < NN) off[idx] = carry + s - v;
            carry += tsum;
        }
        if (lane == 0) off[NN] = carry;
    }
    __syncthreads();

    // match_any slot assignment; write F records directly (weights LDG scattered, L2-hot)
    for (int c = wid; c < NCH; c += 16) {
        int i = c * 32 + lane;
        int f = (i < EE) ? sf[i] : (NN + lane);
        unsigned m = __match_any_sync(0xffffffffu, f);
        int rank = __popc(m & ((1u << lane) - 1u));
        if (i < EE) {
            int slot = off[f] + cb[c * NN + f] + rank;
            eid[slot] = i;
            float w = -wr[tE + i];
            EF rf; rf.wrn0 = w; rf.wrn1 = w; rf.wra = wra[tE + i];
            rf.noff = st[i] * 256;
            g_ef[tE + slot] = rf;
        }
    }
    __syncthreads();

    // F coefficients: diffusion diagonal (bucket-order deterministic sum)
    if (tid < NN) {
        for (int k = off[tid]; k < off[tid + 1]; k++) {
            int e = eid[k];
            dd1 += wd[tE + e] + wda[tE + e];
        }
    }
    if (t == 0 && tid <= NN) g_from_off[tid] = off[tid];
    __syncthreads();   // F coeffs done before T reuses cb/eid/off/tot

    // ================= T side (to-CSR: diffusion records, even-padded) ====
    for (int i = tid; i < NCH * NN; i += 512) cb[i] = 0;
    __syncthreads();
    for (int i = tid; i < EE; i += 512) atomicAdd(&cb[(i >> 5) * NN + st[i]], 1);
    __syncthreads();

    int tcnt = 0;   // true T bucket size (thread tid < NN)
    if (tid < NN) {
        int run = 0;
        #pragma unroll 6
        for (int c = 0; c < NCH; c++) {
            int v = cb[c * NN + tid]; cb[c * NN + tid] = run; run += v;
        }
        tot[tid] = run;
        tcnt = run;
    }
    __syncthreads();

    if (wid == 0) {
        int carry = 0;
        #pragma unroll
        for (int j = 0; j < (NN + 31) / 32; j++) {
            int idx = j * 32 + lane;
            int v = (idx < NN) ? tot[idx] : 0;
            v = (v + 1) & ~1;   // pad bucket sizes to even
            int s = v;
            #pragma unroll
            for (int d = 1; d < 32; d <<= 1) {
                int u = __shfl_up_sync(0xffffffffu, s, d);
                if (lane >= d) s += u;
            }
            int tsum = __shfl_sync(0xffffffffu, s, 31);
            if (idx < NN) off[idx] = carry + s - v;
            carry += tsum;
        }
        if (lane == 0) off[NN] = carry;
    }
    __syncthreads();

    for (int c = wid; c < NCH; c += 16) {
        int i = c * 32 + lane;
        int f = (i < EE) ? st[i] : (NN + lane);
        unsigned m = __match_any_sync(0xffffffffu, f);
        int rank = __popc(m & ((1u << lane) - 1u));
        if (i < EE) {
            int slot = off[f] + cb[c * NN + f] + rank;   // PADDED slot (< EEPAD)
            eid[slot] = i;
            ET rt; rt.wdc = wda[tE + i] - wd[tE + i]; rt.noff = sf[i] * 256;
            g_et[t * EEPAD + slot] = rt;
        }
    }
    // padding slots: odd buckets get one inert tail record
    if (tid < NN && (tot[tid] & 1)) {
        ET rt; rt.wdc = 0.f; rt.noff = 0;
        g_et[t * EEPAD + off[tid] + tot[tid]] = rt;
    }
    __syncthreads();

    // T coefficients: reaction diagonals (true-count, bucket order)
    if (tid < NN) {
        float dr = 0.f, dra = 0.f;
        int k0 = off[tid], k1 = k0 + tcnt;
        for (int k = k0; k < k1; k++) {
            int e = eid[k];
            dr += wr[tE + e]; dra += wra[tE + e];
        }
        float4 c1; c1.x = dr; c1.y = dra; c1.z = dd1; c1.w = br[tN + tid];
        g_c1[tN + tid] = c1;
        float2 c2; c2.x = bra[tN + tid]; c2.y = bd[tN + tid] + bda[tN + tid];
        g_c2[tN + tid] = c2;
    }
    if (t == 0 && tid <= NN) g_to_off[tid] = off[tid];
}

// =====================================================================
// Main kernel (R14 winner, unchanged): each CTA does TWO 128-col L-tiles,
// records staged once via cp.async, bf16 gathers (paired ET loads),
// fp32 diagonal terms, f32x2 FFMA2 accumulation. ~100 KB smem -> 2 CTAs/SM.
// =====================================================================
__global__ __launch_bounds__(NTHREADS, 2)
void rd_main(const float* __restrict__ X, const int* __restrict__ ind,
             float* __restrict__ out) {
    extern __shared__ char smem_raw[];
    uint4*  sef  = reinterpret_cast<uint4*>(smem_raw);              // [EE] EF
    uint2*  sxb  = reinterpret_cast<uint2*>(sef + EE);              // [NN*32] bf16 tile
    ET*     set_ = reinterpret_cast<ET*>(sxb + NN * 32);            // [EEPAD]
    float4* sc1  = reinterpret_cast<float4*>(set_ + EEPAD);         // [NN]
    float2* sc2  = reinterpret_cast<float2*>(sc1 + NN);             // [NN]
    int*    soF  = reinterpret_cast<int*>(sc2 + NN);                // [NN+1]
    int*    soT  = soF + NN + 1;                                    // [NN+1]

    const int b   = blockIdx.y;
    const int t   = ind[b] / RESV;
    const int tid = threadIdx.x;
    const int lane = tid & 31;
    const int wg   = tid >> 5;
    const bool b0  = (b == 0);
    const char* sxbase = reinterpret_cast<const char*>(sxb) + lane * 8;

    // ---- stage records via cp.async ONCE for both halves ----
    {
        unsigned sefA = (unsigned)__cvta_generic_to_shared(sef);
        const char* gef = (const char*)(g_ef + t * EE);
        for (int i = tid; i < EE; i += NTHREADS)
            asm volatile("cp.async.cg.shared.global [%0], [%1], 16;"
                         :: "r"(sefA + i * 16), "l"(gef + (size_t)i * 16));
        unsigned setA = (unsigned)__cvta_generic_to_shared(set_);
        const char* get = (const char*)(g_et + t * EEPAD);
        for (int i = tid; i < EEPAD / 2; i += NTHREADS)   // 965 x 16 B
            asm volatile("cp.async.cg.shared.global [%0], [%1], 16;"
                         :: "r"(setA + i * 16), "l"(get + (size_t)i * 16));
        asm volatile("cp.async.commit_group;");
    }
    if (tid < NN) { sc1[tid] = g_c1[t * NN + tid]; sc2[tid] = g_c2[t * NN + tid]; }
    if (tid >= NN && tid < 2 * NN + 2) {
        int j = tid - NN;
        if (j <= NN) { soF[j] = g_from_off[j]; soT[j] = g_to_off[j]; }
    }
    if (tid == 2 * NN + 2) soT[NN] = g_to_off[NN];

    #pragma unroll 1
    for (int half = 0; half < 2; half++) {
        const int l0q = (blockIdx.x * 2 + half) * LT4;
        const float4* xb4 = reinterpret_cast<const float4*>(X)
                            + (size_t)b * 2 * NN * L4 + l0q;

        // ---- stage bf16 x tile for this half ----
        for (int idx = tid; idx < NN * LT4; idx += NTHREADS) {
            int w = idx >> 5, c = idx & (LT4 - 1);
            float4 v = xb4[(size_t)w * L4 + c];
            uint2 p; p.x = f2bf2(v.y, v.x); p.y = f2bf2(v.w, v.z);
            sxb[w * 32 + c] = p;
        }
        if (half == 0) asm volatile("cp.async.wait_group 0;");
        __syncthreads();

        float4* ob4 = reinterpret_cast<float4*>(out) + (size_t)b * NN * L4 + l0q + lane;
        const uint4* set4 = reinterpret_cast<const uint4*>(set_);

        // row-ahead prefetch of the fp32 diagonal/passthrough vector
        float4 xw = (wg < NN) ? xb4[(size_t)wg * L4 + lane]
                              : make_float4(0.f, 0.f, 0.f, 0.f);

        for (int w = wg; w < NN; w += NWARPS) {
            // kick next row's LDG before the long LDS loops
            int wn = w + NWARPS;
            float4 xwn = xw;
            if (wn < NN) xwn = xb4[(size_t)wn * L4 + lane];

            float4 c1 = sc1[w];
            float2 c2 = sc2[w];
            float dra = b0 ? 0.f : c1.y;   // batch 0: RWa diagonal is exactly zero

            unsigned long long xw01 = pk2(xw.x, xw.y), xw23 = pk2(xw.z, xw.w);
            unsigned long long drp  = pk2(c1.x, c1.x), brp  = pk2(c1.w, c1.w);
            unsigned long long drap = pk2(dra,  dra ), brap = pk2(c2.x, c2.x);
            unsigned long long dlp  = pk2(c1.z, c1.z), bdp  = pk2(c2.y, c2.y);

            unsigned long long r01 = brp,  r23 = brp;
            unsigned long long ra01 = brap, ra23 = brap;
            unsigned long long li01 = bdp,  li23 = bdp;
            fma2(r01, drp, xw01);   fma2(r23, drp, xw23);
            fma2(ra01, drap, xw01); fma2(ra23, drap, xw23);
            fma2(li01, dlp, xw01);  fma2(li23, dlp, xw23);

            int k0 = soF[w], k1 = soF[w + 1];
            #pragma unroll 8
            for (int k = k0; k < k1; k++) {
                uint4 e = sef[k];                     // broadcast LDS.128 (1 wf)
                unsigned long long wrp  = pkpair(e.x, e.y);   // pair alias
                unsigned long long wrap = pkpair(e.z, e.z);   // 1 MOV
                uint2 xv = *reinterpret_cast<const uint2*>(sxbase + (int)e.w);
                unsigned long long x01 = bf2f2(xv.x), x23 = bf2f2(xv.y);
                fma2(r01, wrp, x01);   fma2(r23, wrp, x23);
                fma2(ra01, wrap, x01); fma2(ra23, wrap, x23);
            }

            // to-CSR buckets are even-sized: process edge PAIRS, one LDS.128
            // record load per pair (padding entries have wdc = 0).
            k0 = soT[w] >> 1; k1 = soT[w + 1] >> 1;
            #pragma unroll 4
            for (int k = k0; k < k1; k++) {
                uint4 e = set4[k];                    // 2 ET records (1 wf)
                uint2 xv0 = *reinterpret_cast<const uint2*>(sxbase + (int)e.y);
                uint2 xv1 = *reinterpret_cast<const uint2*>(sxbase + (int)e.w);
                unsigned long long wd0 = pkpair(e.x, e.x);
                unsigned long long wd1 = pkpair(e.z, e.z);
                fma2(li01, wd0, bf2f2(xv0.x)); fma2(li23, wd0, bf2f2(xv0.y));
                fma2(li01, wd1, bf2f2(xv1.x)); fma2(li23, wd1, bf2f2(xv1.y));
            }

            float r0, r1, r2, r3, a0, a1, a2, a3, l0, l1, l2, l3;
            upk2(r01, r0, r1);   upk2(r23, r2, r3);
            upk2(ra01, a0, a1);  upk2(ra23, a2, a3);
            upk2(li01, l0, l1);  upk2(li23, l2, l3);

            float4 o;
            o.x = ftanh(r0) + ftanh(a0) + l0;
            o.y = ftanh(r1) + ftanh(a1) + l1;
            o.z = ftanh(r2) + ftanh(a2) + l2;
            o.w = ftanh(r3) + ftanh(a3) + l3;
            ob4[(size_t)w * L4] = o;

            xw = xwn;
        }
        __syncthreads();   // all reads of sxb done before half=1 overwrites it
    }
}

// ---------------- launch ----------------
extern "C" void kernel_launch(void* const* d_in, const int* in_sizes, int n_in,
                              void* d_out, int out_size) {
    const float* X   = (const float*)d_in[0];
    const int*   ind = (const int*)d_in[1];
    const int*   ef  = (const int*)d_in[2];
    const int*   et  = (const int*)d_in[3];
    const float* wr  = (const float*)d_in[4];
    const float* wd  = (const float*)d_in[5];
    const float* wra = (const float*)d_in[6];
    const float* wda = (const float*)d_in[7];
    const float* br  = (const float*)d_in[8];
    const float* bd  = (const float*)d_in[9];
    const float* bra = (const float*)d_in[10];
    const float* bda = (const float*)d_in[11];
    float* out = (float*)d_out;

    const int psmem = (2 * EE + NCH * NN + EEPAD + (NN + 1) + NN)
                      * (int)sizeof(int);             // ~67.9 KB
    const int smem  = EE * (int)sizeof(EF)          // 27,552 EF
                    + NN * 32 * (int)sizeof(uint2)  // 52,992 bf16 tile
                    + EEPAD * (int)sizeof(ET)       // 15,440 ET (padded)
                    + NN * (int)sizeof(float4)      //  3,312 c1
                    + NN * (int)sizeof(float2)      //  1,656 c2
                    + 2 * (NN + 1) * (int)sizeof(int); // 1,664 offsets => 102,616 B
    cudaFuncSetAttribute(rd_prep, cudaFuncAttributeMaxDynamicSharedMemorySize, psmem);
    cudaFuncSetAttribute(rd_main, cudaFuncAttributeMaxDynamicSharedMemorySize, smem);

    rd_prep<<<TT, 512, psmem>>>(ef, et, wr, wd, wra, wda, br, bd, bra, bda);

    dim3 grid(LL / (LT4 * 4 * 2), BB);   // (8, 64) — two L-tiles per CTA
    rd_main<<<grid, NTHREADS, smem>>>(X, ind, out);
}

// round 17
// speedup vs baseline: 1.0296x; 1.0296x over previous
#include <cuda_runtime.h>

#define NN 207
#define EE 1722
#define TT 24
#define BB 64
#define LL 2048
#define RESV 12
#define L4 (LL / 4)      // 512 float4 per row
#define LT4 32           // float4 per L-tile (= 128 floats)
#define NTHREADS 640     // main kernel: 20 warps, 2 CTAs/SM (40 warps, reg-capped 51)
#define NWARPS (NTHREADS / 32)
#define NCH ((EE + 31) / 32)   // 54 edge chunks of 32
#define EEPAD 1930             // to-CSR entries incl. even-padding

// ---------------- device scratch (no allocation allowed) ----------------
struct __align__(16) EF { float wrn0; float wrn1; float wra; int noff; };
struct __align__(8)  ET { float wdc; int noff; };

__device__ EF     g_ef[TT * EE];         // from-CSR ordered, per t (reaction gathers)
__device__ ET     g_et[TT * EEPAD];      // to-CSR ordered, per t (diffusion, even-padded)
__device__ float4 g_c1[TT * NN];         // (dr, dra, dd+dda+1, br)
__device__ float2 g_c2[TT * NN];         // (bra, bd+bda)
__device__ int    g_from_off[NN + 1];
__device__ int    g_to_off[NN + 1];      // PADDED offsets

// ---------------- packed helpers ----------------
__device__ __forceinline__ unsigned long long pk2(float a, float b) {
    unsigned long long r;
    asm("mov.b64 %0, {%1, %2};" : "=l"(r) : "f"(a), "f"(b));
    return r;
}
__device__ __forceinline__ unsigned long long pkpair(unsigned a, unsigned b) {
    unsigned long long r;
    asm("mov.b64 %0, {%1, %2};" : "=l"(r) : "r"(a), "r"(b));
    return r;
}
__device__ __forceinline__ void upk2(unsigned long long v, float& a, float& b) {
    asm("mov.b64 {%0, %1}, %2;" : "=f"(a), "=f"(b) : "l"(v));
}
__device__ __forceinline__ void fma2(unsigned long long& d,
                                     unsigned long long a, unsigned long long b) {
    asm("fma.rn.f32x2 %0, %1, %2, %0;" : "+l"(d) : "l"(a), "l"(b));
}
// packed bf16 pair -> f32x2 (AND is load-bearing for precision)
__device__ __forceinline__ unsigned long long bf2f2(unsigned v) {
    unsigned long long r;
    asm("{\n\t.reg .b32 lo, hi;\n\t"
        "shl.b32 lo, %1, 16;\n\t"
        "and.b32 hi, %1, 0xFFFF0000;\n\t"
        "mov.b64 %0, {lo, hi};\n\t}" : "=l"(r) : "r"(v));
    return r;
}
__device__ __forceinline__ unsigned f2bf2(float c1, float c0) {
    unsigned r;
    asm("cvt.rn.bf16x2.f32 %0, %1, %2;" : "=r"(r) : "f"(c1), "f"(c0));
    return r;
}
__device__ __forceinline__ float ftanh(float x) {
    float y;
    asm("tanh.approx.f32 %0, %1;" : "=f"(y) : "f"(x));
    return y;
}

// =====================================================================
// Prepass: 48 blocks = (t, side). Each block builds one CSR side for one
// t (chunk-parallel) and writes records + its half of the coefficients.
// F/T blocks write disjoint floats of g_c1/g_c2 — no race.
// =====================================================================
__global__ __launch_bounds__(512)
void rd_prep(const int* __restrict__ ef, const int* __restrict__ et,
             const float* __restrict__ wr,  const float* __restrict__ wd,
             const float* __restrict__ wra, const float* __restrict__ wda,
             const float* __restrict__ br,  const float* __restrict__ bd,
             const float* __restrict__ bra, const float* __restrict__ bda) {
    extern __shared__ int sh[];
    int* sf  = sh;               // [EE]
    int* st  = sf + EE;          // [EE]
    int* cb  = st + EE;          // [NCH*NN]
    int* eid = cb + NCH * NN;    // [EEPAD]
    int* off = eid + EEPAD;      // [NN+1]
    int* tot = off + NN + 1;     // [NN]

    const int t    = blockIdx.x >> 1;
    const bool isT = blockIdx.x & 1;
    const int tid = threadIdx.x;
    const int lane = tid & 31;
    const int wid  = tid >> 5;
    const int tE  = t * EE;
    const int tN  = t * NN;

    for (int i = tid; i < EE; i += 512) { sf[i] = ef[i]; st[i] = et[i]; }
    for (int i = tid; i < NCH * NN; i += 512) cb[i] = 0;
    __syncthreads();

    const int* key = isT ? st : sf;
    for (int i = tid; i < EE; i += 512) atomicAdd(&cb[(i >> 5) * NN + key[i]], 1);
    __syncthreads();

    int tcnt = 0;
    if (tid < NN) {
        int run = 0;
        #pragma unroll 6
        for (int c = 0; c < NCH; c++) {
            int v = cb[c * NN + tid]; cb[c * NN + tid] = run; run += v;
        }
        tot[tid] = run;
        tcnt = run;
    }
    __syncthreads();

    if (wid == 0) {
        int carry = 0;
        #pragma unroll
        for (int j = 0; j < (NN + 31) / 32; j++) {
            int idx = j * 32 + lane;
            int v = (idx < NN) ? tot[idx] : 0;
            if (isT) v = (v + 1) & ~1;   // even-pad T buckets
            int s = v;
            #pragma unroll
            for (int d = 1; d < 32; d <<= 1) {
                int u = __shfl_up_sync(0xffffffffu, s, d);
                if (lane >= d) s += u;
            }
            int tsum = __shfl_sync(0xffffffffu, s, 31);
            if (idx < NN) off[idx] = carry + s - v;
            carry += tsum;
        }
        if (lane == 0) off[NN] = carry;
    }
    __syncthreads();

    // match_any slot assignment; write records directly
    for (int c = wid; c < NCH; c += 16) {
        int i = c * 32 + lane;
        int f = (i < EE) ? key[i] : (NN + lane);
        unsigned m = __match_any_sync(0xffffffffu, f);
        int rank = __popc(m & ((1u << lane) - 1u));
        if (i < EE) {
            int slot = off[f] + cb[c * NN + f] + rank;
            eid[slot] = i;
            if (isT) {
                ET rt; rt.wdc = wda[tE + i] - wd[tE + i]; rt.noff = sf[i] * 256;
                g_et[t * EEPAD + slot] = rt;
            } else {
                float w = -wr[tE + i];
                EF rf; rf.wrn0 = w; rf.wrn1 = w; rf.wra = wra[tE + i];
                rf.noff = st[i] * 256;
                g_ef[tE + slot] = rf;
            }
        }
    }
    if (isT && tid < NN && (tot[tid] & 1)) {   // inert padding record
        ET rt; rt.wdc = 0.f; rt.noff = 0;
        g_et[t * EEPAD + off[tid] + tot[tid]] = rt;
    }
    __syncthreads();

    // coefficients (bucket-order deterministic sums; disjoint float writes)
    if (tid < NN) {
        float* c1f = reinterpret_cast<float*>(g_c1 + tN + tid);
        if (isT) {
            float dr = 0.f, dra = 0.f;
            int k0 = off[tid], k1 = k0 + tcnt;
            for (int k = k0; k < k1; k++) {
                int e = eid[k];
                dr += wr[tE + e]; dra += wra[tE + e];
            }
            c1f[0] = dr; c1f[1] = dra;
            float2 c2; c2.x = bra[tN + tid]; c2.y = bd[tN + tid] + bda[tN + tid];
            g_c2[tN + tid] = c2;
        } else {
            float dd1 = 1.f;
            for (int k = off[tid]; k < off[tid + 1]; k++) {
                int e = eid[k];
                dd1 += wd[tE + e] + wda[tE + e];
            }
            c1f[2] = dd1; c1f[3] = br[tN + tid];
        }
    }
    if (t == 0 && tid <= NN) {
        if (isT) g_to_off[tid] = off[tid];
        else     g_from_off[tid] = off[tid];
    }
}

// =====================================================================
// Main kernel: 640 threads (20 warps), reg-capped for 2 CTAs/SM = 40
// warps. Each CTA does TWO 128-col L-tiles; records staged once via
// cp.async; bf16 gathers; diag terms applied AFTER the edge loops so the
// row's fp32 LDG (issued at loop top) is hidden with no prefetch regs.
// =====================================================================
__global__ __launch_bounds__(NTHREADS, 2)
void rd_main(const float* __restrict__ X, const int* __restrict__ ind,
             float* __restrict__ out) {
    extern __shared__ char smem_raw[];
    uint4*  sef  = reinterpret_cast<uint4*>(smem_raw);              // [EE] EF
    uint2*  sxb  = reinterpret_cast<uint2*>(sef + EE);              // [NN*32] bf16 tile
    ET*     set_ = reinterpret_cast<ET*>(sxb + NN * 32);            // [EEPAD]
    float4* sc1  = reinterpret_cast<float4*>(set_ + EEPAD);         // [NN]
    float2* sc2  = reinterpret_cast<float2*>(sc1 + NN);             // [NN]
    int*    soF  = reinterpret_cast<int*>(sc2 + NN);                // [NN+1]
    int*    soT  = soF + NN + 1;                                    // [NN+1]

    const int b   = blockIdx.y;
    const int t   = ind[b] / RESV;
    const int tid = threadIdx.x;
    const int lane = tid & 31;
    const int wg   = tid >> 5;
    const bool b0  = (b == 0);
    const char* sxbase = reinterpret_cast<const char*>(sxb) + lane * 8;

    // ---- stage records via cp.async ONCE for both halves ----
    {
        unsigned sefA = (unsigned)__cvta_generic_to_shared(sef);
        const char* gef = (const char*)(g_ef + t * EE);
        for (int i = tid; i < EE; i += NTHREADS)
            asm volatile("cp.async.cg.shared.global [%0], [%1], 16;"
                         :: "r"(sefA + i * 16), "l"(gef + (size_t)i * 16));
        unsigned setA = (unsigned)__cvta_generic_to_shared(set_);
        const char* get = (const char*)(g_et + t * EEPAD);
        for (int i = tid; i < EEPAD / 2; i += NTHREADS)
            asm volatile("cp.async.cg.shared.global [%0], [%1], 16;"
                         :: "r"(setA + i * 16), "l"(get + (size_t)i * 16));
        asm volatile("cp.async.commit_group;");
    }
    if (tid < NN) { sc1[tid] = g_c1[t * NN + tid]; sc2[tid] = g_c2[t * NN + tid]; }
    if (tid >= NN && tid < 2 * NN + 2) {
        int j = tid - NN;
        if (j <= NN) { soF[j] = g_from_off[j]; soT[j] = g_to_off[j]; }
    }
    if (tid == 2 * NN + 2) soT[NN] = g_to_off[NN];

    #pragma unroll 1
    for (int half = 0; half < 2; half++) {
        const int l0q = (blockIdx.x * 2 + half) * LT4;
        const float4* xb4 = reinterpret_cast<const float4*>(X)
                            + (size_t)b * 2 * NN * L4 + l0q;

        // ---- stage bf16 x tile for this half ----
        for (int idx = tid; idx < NN * LT4; idx += NTHREADS) {
            int w = idx >> 5, c = idx & (LT4 - 1);
            float4 v = xb4[(size_t)w * L4 + c];
            uint2 p; p.x = f2bf2(v.y, v.x); p.y = f2bf2(v.w, v.z);
            sxb[w * 32 + c] = p;
        }
        if (half == 0) asm volatile("cp.async.wait_group 0;");
        __syncthreads();

        float4* ob4 = reinterpret_cast<float4*>(out) + (size_t)b * NN * L4 + l0q + lane;
        const uint4* set4 = reinterpret_cast<const uint4*>(set_);

        for (int w = wg; w < NN; w += NWARPS) {
            // fp32 diag/passthrough vector: LDG issued now, consumed after loops
            float4 xw = xb4[(size_t)w * L4 + lane];
            float4 c1 = sc1[w];
            float2 c2 = sc2[w];

            unsigned long long r01 = pk2(c1.w, c1.w), r23 = r01;
            unsigned long long ra01 = pk2(c2.x, c2.x), ra23 = ra01;
            unsigned long long li01 = pk2(c2.y, c2.y), li23 = li01;

            int k0 = soF[w], k1 = soF[w + 1];
            #pragma unroll 8
            for (int k = k0; k < k1; k++) {
                uint4 e = sef[k];                     // broadcast LDS.128 (1 wf)
                unsigned long long wrp  = pkpair(e.x, e.y);
                unsigned long long wrap = pkpair(e.z, e.z);
                uint2 xv = *reinterpret_cast<const uint2*>(sxbase + (int)e.w);
                unsigned long long x01 = bf2f2(xv.x), x23 = bf2f2(xv.y);
                fma2(r01, wrp, x01);   fma2(r23, wrp, x23);
                fma2(ra01, wrap, x01); fma2(ra23, wrap, x23);
            }

            // even-sized T buckets: edge PAIRS, one LDS.128 per pair
            k0 = soT[w] >> 1; k1 = soT[w + 1] >> 1;
            #pragma unroll 4
            for (int k = k0; k < k1; k++) {
                uint4 e = set4[k];                    // 2 ET records (1 wf)
                uint2 xv0 = *reinterpret_cast<const uint2*>(sxbase + (int)e.y);
                uint2 xv1 = *reinterpret_cast<const uint2*>(sxbase + (int)e.w);
                unsigned long long wd0 = pkpair(e.x, e.x);
                unsigned long long wd1 = pkpair(e.z, e.z);
                fma2(li01, wd0, bf2f2(xv0.x)); fma2(li23, wd0, bf2f2(xv0.y));
                fma2(li01, wd1, bf2f2(xv1.x)); fma2(li23, wd1, bf2f2(xv1.y));
            }

            // diagonal + passthrough (batch 0: RWa diagonal exactly zero)
            float dra = b0 ? 0.f : c1.y;
            unsigned long long xw01 = pk2(xw.x, xw.y), xw23 = pk2(xw.z, xw.w);
            unsigned long long drp  = pk2(c1.x, c1.x);
            unsigned long long drap = pk2(dra,  dra );
            unsigned long long dlp  = pk2(c1.z, c1.z);
            fma2(r01, drp, xw01);   fma2(r23, drp, xw23);
            fma2(ra01, drap, xw01); fma2(ra23, drap, xw23);
            fma2(li01, dlp, xw01);  fma2(li23, dlp, xw23);

            float r0, r1, r2, r3, a0, a1, a2, a3, l0, l1, l2, l3;
            upk2(r01, r0, r1);   upk2(r23, r2, r3);
            upk2(ra01, a0, a1);  upk2(ra23, a2, a3);
            upk2(li01, l0, l1);  upk2(li23, l2, l3);

            float4 o;
            o.x = ftanh(r0) + ftanh(a0) + l0;
            o.y = ftanh(r1) + ftanh(a1) + l1;
            o.z = ftanh(r2) + ftanh(a2) + l2;
            o.w = ftanh(r3) + ftanh(a3) + l3;
            ob4[(size_t)w * L4] = o;
        }
        __syncthreads();   // all reads of sxb done before half=1 overwrites it
    }
}

// ---------------- launch ----------------
extern "C" void kernel_launch(void* const* d_in, const int* in_sizes, int n_in,
                              void* d_out, int out_size) {
    const float* X   = (const float*)d_in[0];
    const int*   ind = (const int*)d_in[1];
    const int*   ef  = (const int*)d_in[2];
    const int*   et  = (const int*)d_in[3];
    const float* wr  = (const float*)d_in[4];
    const float* wd  = (const float*)d_in[5];
    const float* wra = (const float*)d_in[6];
    const float* wda = (const float*)d_in[7];
    const float* br  = (const float*)d_in[8];
    const float* bd  = (const float*)d_in[9];
    const float* bra = (const float*)d_in[10];
    const float* bda = (const float*)d_in[11];
    float* out = (float*)d_out;

    const int psmem = (2 * EE + NCH * NN + EEPAD + (NN + 1) + NN)
                      * (int)sizeof(int);             // ~67.9 KB
    const int smem  = EE * (int)sizeof(EF)          // 27,552 EF
                    + NN * 32 * (int)sizeof(uint2)  // 52,992 bf16 tile
                    + EEPAD * (int)sizeof(ET)       // 15,440 ET (padded)
                    + NN * (int)sizeof(float4)      //  3,312 c1
                    + NN * (int)sizeof(float2)      //  1,656 c2
                    + 2 * (NN + 1) * (int)sizeof(int); // 1,664 offsets => 102,616 B
    cudaFuncSetAttribute(rd_prep, cudaFuncAttributeMaxDynamicSharedMemorySize, psmem);
    cudaFuncSetAttribute(rd_main, cudaFuncAttributeMaxDynamicSharedMemorySize, smem);

    rd_prep<<<TT * 2, 512, psmem>>>(ef, et, wr, wd, wra, wda, br, bd, bra, bda);

    dim3 grid(LL / (LT4 * 4 * 2), BB);   // (8, 64) — two L-tiles per CTA
    rd_main<<<grid, NTHREADS, smem>>>(X, ind, out);
}